// round 14
// baseline (speedup 1.0000x reference)
#include <cuda_runtime.h>
#include <cuda_fp16.h>
#include <math.h>
#include <cstdint>

#define B_TOTAL 131072
#define SD 128
#define AD 32
#define TILE_M 64
#define NTILES 2048            // per branch
#define NTHREADS 256

__device__ float d_M[2][256];
// fp16 B fragments GEMM1 in ldmatrix-native layout (uint32 units):
// [br][ks(10)][nw(4)][g(4)][m(4)][r(8)][c(4)]  (matrix = 128B)
__device__ uint32_t d_Bfrag[2 * 10 * 4 * 4 * 4 * 32];
// fp16 B fragments GEMM2 (W2^T, n=8 padded): [br][ks(16)][lane(32)][2] half2
__device__ __half2 d_W2frag[2 * 16 * 32 * 2];

// ---- smem layout (byte offsets), per CTA ----
#define OFF_B     0            // 81920B: full W1 frags (ldmatrix layout)
#define OFF_A     81920        // [64][168] halfs = 21504B (single buffer)
#define OFF_W2F   103424       // 4096B
#define OFF_B1S   107520       // 256 floats = 1024B
#define OFF_MS    108544       // 16x17 floats -> 1152B reserved
#define OFF_QPART 109696       // fp16 qpart, double buffered: 2*4*64*2*4B = 4096B
#define OFF_B2S   113792       // 16B
#define OFF_PP    113808       // 8B
#define SMEM_BYTES 113824      // x2 CTAs = 227648 <= 228KB

#define A_PITCH 168            // halfs per row (160 data + 8 pad)
#define A_PITCH_B 336          // bytes

__device__ __forceinline__ uint32_t smem_u32(const void* p) {
    uint32_t a;
    asm("{ .reg .u64 t; cvta.to.shared.u64 t, %1; cvt.u32.u64 %0, t; }" : "=r"(a) : "l"(p));
    return a;
}
#define CP_ASYNC16(dst, src) \
    asm volatile("cp.async.cg.shared.global [%0], [%1], 16;" :: "r"(dst), "l"(src) : "memory")
#define CP_COMMIT() asm volatile("cp.async.commit_group;" ::: "memory")
#define CP_WAIT0()  asm volatile("cp.async.wait_group 0;" ::: "memory")

#define LDSM_X4(r0, r1, r2, r3, addr) \
    asm volatile("ldmatrix.sync.aligned.m8n8.x4.shared.b16 {%0,%1,%2,%3}, [%4];" \
        : "=r"(r0), "=r"(r1), "=r"(r2), "=r"(r3) : "r"(addr))

__device__ __forceinline__ void mma_f16(float* d, const uint32_t* a,
                                        uint32_t b0, uint32_t b1) {
    asm volatile(
        "mma.sync.aligned.m16n8k16.row.col.f32.f16.f16.f32 "
        "{%0,%1,%2,%3}, {%4,%5,%6,%7}, {%8,%9}, {%0,%1,%2,%3};"
        : "+f"(d[0]), "+f"(d[1]), "+f"(d[2]), "+f"(d[3])
        : "r"(a[0]), "r"(a[1]), "r"(a[2]), "r"(a[3]), "r"(b0), "r"(b1));
}
__device__ __forceinline__ uint32_t h2u(__half2 h) { return *(uint32_t*)&h; }

// ---------------------------------------------------------------------------
// Setup: blocks 0,1 -> M; 2..81 -> W1 frags (ldmatrix layout); 82 -> W2 frags.
// ---------------------------------------------------------------------------
__global__ void setup_kernel(const float* __restrict__ qw1,
                             const float* __restrict__ qw2,
                             const float* __restrict__ W1a,
                             const float* __restrict__ W1b,
                             const float* __restrict__ W2a,
                             const float* __restrict__ W2b) {
    if (blockIdx.x < 2) {
        const int br = blockIdx.x;
        const int t  = threadIdx.x;
        const int j  = t >> 4;
        const int m  = t & 15;
        const float* qw = br ? qw2 : qw1;
        __shared__ float Ur[16][17];
        __shared__ float Ui[16][17];

        float sr = (m == j) ? 1.f : 0.f;
        float si = 0.f;

        for (int l = 0; l < 2; ++l) {
            #pragma unroll
            for (int i = 0; i < 4; ++i) {
                const int st = 8 >> i;
                float cc, ss, pr, pi;
                sincosf(0.5f * qw[(l * 4 + i) * 3 + 0], &ss, &cc);   // RX
                pr = __shfl_xor_sync(0xffffffffu, sr, st);
                pi = __shfl_xor_sync(0xffffffffu, si, st);
                { float nr = cc * sr + ss * pi, ni = cc * si - ss * pr;
                  sr = nr; si = ni; }
                sincosf(0.5f * qw[(l * 4 + i) * 3 + 1], &ss, &cc);   // RY
                pr = __shfl_xor_sync(0xffffffffu, sr, st);
                pi = __shfl_xor_sync(0xffffffffu, si, st);
                { const float e = (m & st) ? ss : -ss;
                  float nr = cc * sr + e * pr, ni = cc * si + e * pi;
                  sr = nr; si = ni; }
                sincosf(0.5f * qw[(l * 4 + i) * 3 + 2], &ss, &cc);   // RZ
                { const float e = (m & st) ? -ss : ss;
                  float nr = cc * sr + e * si, ni = cc * si - e * sr;
                  sr = nr; si = ni; }
            }
            #pragma unroll
            for (int e = 0; e < 4; ++e) {
                const int sc  = 8 >> e;
                const int stt = 8 >> ((e + 1) & 3);
                const float pr = __shfl_xor_sync(0xffffffffu, sr, stt);
                const float pi = __shfl_xor_sync(0xffffffffu, si, stt);
                if (m & sc) { sr = pr; si = pi; }
            }
        }
        Ur[m][j] = sr;
        Ui[m][j] = si;
        __syncthreads();
        {
            const int i = t >> 4, jj = t & 15;
            float acc = 0.f;
            #pragma unroll
            for (int k = 0; k < 16; ++k) {
                const float d = (k < 8) ? 1.f : -1.f;
                acc += d * (Ur[k][i] * Ur[k][jj] + Ui[k][i] * Ui[k][jj]);
            }
            d_M[br][i * 16 + jj] = acc;
        }
    } else if (blockIdx.x < 82) {
        // ldmatrix-native B fragment layout.
        // idx decomposes to (br, ks, nw, g, r, c); each thread writes m=0..3.
        const int idx = (blockIdx.x - 2) * 256 + threadIdx.x;
        if (idx >= 10240) return;
        const int c  = idx & 3;
        const int r  = (idx >> 2) & 7;
        const int g  = (idx >> 5) & 3;
        const int nw = (idx >> 7) & 3;
        const int t  = idx >> 9;           // br*10 + ks
        const int ks = t % 10;
        const int br = t / 10;
        const float* W1 = br ? W1b : W1a;
        #pragma unroll
        for (int m = 0; m < 4; ++m) {
            const int n = (nw * 8 + 2 * g + (m >> 1)) * 8 + r;
            const int k = ks * 16 + c * 2 + (m & 1) * 8;
            const __half2 v = __floats2half2_rn(W1[n * 160 + k], W1[n * 160 + k + 1]);
            const int dst = ((((br * 10 + ks) * 4 + nw) * 4 + g) * 4 + m) * 32
                          + r * 4 + c;
            d_Bfrag[dst] = *(const uint32_t*)&v;
        }
    } else {
        #pragma unroll
        for (int rep = 0; rep < 4; ++rep) {
            const int idx = threadIdx.x + rep * 256;   // 0..1023
            const int br   = idx >> 9;
            const int rem  = idx & 511;
            const int ks   = rem >> 5;
            const int lane = rem & 31;
            const float* W2 = br ? W2b : W2a;
            const int n  = lane >> 2;
            const int k0 = ks * 16 + (lane & 3) * 2;
            __half2 v0 = __floats2half2_rn(0.f, 0.f), v1 = v0;
            if (n < 4) {
                v0 = __floats2half2_rn(W2[n * 256 + k0],     W2[n * 256 + k0 + 1]);
                v1 = __floats2half2_rn(W2[n * 256 + k0 + 8], W2[n * 256 + k0 + 9]);
            }
            d_W2frag[idx * 2]     = v0;
            d_W2frag[idx * 2 + 1] = v1;
        }
    }
}

// ---------------------------------------------------------------------------
// Persistent fused critic, 2 CTAs/SM. R13 base + ldmatrix B loads (half the
// mainloop MIO issues) + qpart stores hoisted before bar1 (tail = stsA only).
// ---------------------------------------------------------------------------
__global__ __launch_bounds__(NTHREADS, 2)
void critic_mma(const float* __restrict__ state,
                const float* __restrict__ action,
                const float* __restrict__ b1a, const float* __restrict__ b2a,
                const float* __restrict__ b1b, const float* __restrict__ b2b,
                const float* __restrict__ pwa, const float* __restrict__ pba,
                const float* __restrict__ pwb, const float* __restrict__ pbb,
                float* __restrict__ out) {
    extern __shared__ char smem[];
    const uint32_t sb = smem_u32(smem);
    const int tid  = threadIdx.x;
    const int w    = tid >> 5;
    const int lane = tid & 31;
    const int mw   = w >> 2;        // 0..1
    const int nw   = w & 3;         // 0..3
    const int gid  = lane >> 2;
    const int tig  = lane & 3;

    const int br   = blockIdx.x & 1;
    const int cid  = blockIdx.x >> 1;
    const int ncta = gridDim.x >> 1;
    const int per  = NTILES / ncta;
    const int rem  = NTILES % ncta;
    const int t0   = cid * per + (cid < rem ? cid : rem);
    const int cnt  = per + (cid < rem ? 1 : 0);

    const float* b1 = br ? b1b : b1a;
    const float* b2 = br ? b2b : b2a;
    const float* pw = br ? pwb : pwa;
    const float* pb = br ? pbb : pba;

    float*   b1s    = (float*)(smem + OFF_B1S);
    float*   Ms     = (float*)(smem + OFF_MS);      // pitch 17
    __half2* qpart2 = (__half2*)(smem + OFF_QPART); // [2][4][64][2] half2
    float*   b2s    = (float*)(smem + OFF_B2S);
    float*   pp     = (float*)(smem + OFF_PP);
    __half*  As     = (__half*)(smem + OFF_A);

    // --- A staging: 64 x 160 fp32 -> regs -> fp16 smem ---
    float4 aregs[10];
    auto ldgA = [&](int rowbase) {
        #pragma unroll
        for (int ch = 0; ch < 5; ++ch)
            #pragma unroll
            for (int i = 0; i < 2; ++i) {
                const int e = tid + i * NTHREADS;     // 0..511
                const int r = e >> 3, seg = e & 7;    // 64 rows x 8 segs
                const float* src = (ch < 4)
                    ? state  + (size_t)(rowbase + r) * SD + ch * 32 + seg * 4
                    : action + (size_t)(rowbase + r) * AD + seg * 4;
                aregs[ch * 2 + i] = *(const float4*)src;
            }
    };
    auto stsA = [&]() {
        #pragma unroll
        for (int ch = 0; ch < 5; ++ch)
            #pragma unroll
            for (int i = 0; i < 2; ++i) {
                const int e = tid + i * NTHREADS;
                const int r = e >> 3, seg = e & 7;
                const float4 v = aregs[ch * 2 + i];
                __half2 h0 = __floats2half2_rn(v.x, v.y);
                __half2 h1 = __floats2half2_rn(v.z, v.w);
                *(uint2*)(As + r * A_PITCH + ch * 32 + seg * 4) =
                    make_uint2(h2u(h0), h2u(h1));
            }
    };

    // --- prologue: B frags (80KB), W2 frags, tables, A(tile0) ---
    {
        const uint32_t* srcB = d_Bfrag + (size_t)br * 20480;
        #pragma unroll
        for (int i = 0; i < 20; ++i) {
            const int e = tid + i * NTHREADS;         // 0..5119 16B segs
            CP_ASYNC16(sb + OFF_B + e * 16, srcB + e * 4);
        }
        CP_ASYNC16(sb + OFF_W2F + tid * 16, d_W2frag + br * 1024 + tid * 4);
        CP_COMMIT();
    }
    ldgA(t0 * TILE_M);
    stsA();
    b1s[tid] = b1[tid];
    Ms[(tid >> 4) * 17 + (tid & 15)] = d_M[br][tid];
    if (tid < 4) b2s[tid] = b2[tid];
    if (tid == 0) { pp[0] = pw[0]; pp[1] = pb[0]; }
    CP_WAIT0();
    __syncthreads();

    const char* W2Fs = smem + OFF_W2F;

    // per-lane address pieces
    const uint32_t lrow  = (lane & 7) + (((lane >> 3) & 1) << 3);
    const uint32_t lkofs = (lane >> 4) * 16;   // bytes
    const uint32_t Ab0 = sb + OFF_A + (mw * 32 + lrow) * A_PITCH_B + lkofs;
    // ldmatrix B: lane -> matrix (lane>>3), row (lane&7)
    const uint32_t Bb0 = sb + OFF_B + nw * 2048
                       + ((lane >> 3) << 7) + ((lane & 7) << 4);

    int p = 0;
    for (int it = 0; it < cnt; ++it) {
        const int rowbase = (t0 + it) * TILE_M;
        const int nrb = (it + 1 < cnt) ? (t0 + it + 1) * TILE_M : rowbase;

        float acc[2][8][4];
        #pragma unroll
        for (int mt = 0; mt < 2; ++mt)
            #pragma unroll
            for (int nt = 0; nt < 8; ++nt)
                #pragma unroll
                for (int i = 0; i < 4; ++i) acc[mt][nt][i] = 0.f;

        // ---- GEMM1: 10 ksteps, barrier-free; ldgA(next) at ks 7 ----
        #pragma unroll
        for (int ks = 0; ks < 10; ++ks) {
            if (ks == 7) ldgA(nrb);
            uint32_t a[2][4];
            #pragma unroll
            for (int mt = 0; mt < 2; ++mt)
                LDSM_X4(a[mt][0], a[mt][1], a[mt][2], a[mt][3],
                        Ab0 + mt * 16 * A_PITCH_B + ks * 32);
            #pragma unroll
            for (int g = 0; g < 4; ++g) {
                uint32_t b[4];
                LDSM_X4(b[0], b[1], b[2], b[3],
                        Bb0 + ks * 8192 + g * 512);
                #pragma unroll
                for (int mt = 0; mt < 2; ++mt) {
                    mma_f16(acc[mt][2 * g],     a[mt], b[0], b[1]);
                    mma_f16(acc[mt][2 * g + 1], a[mt], b[2], b[3]);
                }
            }
        }

        // ---- GEMM2 (regs + constant smem; absorbs barrier skew) ----
        float acc2a[2][4], acc2b[2][4];
        #pragma unroll
        for (int mt = 0; mt < 2; ++mt)
            #pragma unroll
            for (int i = 0; i < 4; ++i) { acc2a[mt][i] = 0.f; acc2b[mt][i] = 0.f; }

        #pragma unroll
        for (int ks2 = 0; ks2 < 4; ++ks2) {
            const int c0 = nw * 64 + ks2 * 16 + tig * 2;
            const float bb0 = b1s[c0],     bb1 = b1s[c0 + 1];
            const float bb2 = b1s[c0 + 8], bb3 = b1s[c0 + 9];
            const uint2 bv = *(const uint2*)(W2Fs + ((nw * 4 + ks2) * 32 + lane) * 8);
            #pragma unroll
            for (int mt = 0; mt < 2; ++mt) {
                const float* p0 = acc[mt][2 * ks2];
                const float* p1 = acc[mt][2 * ks2 + 1];
                uint32_t af[4];
                af[0] = h2u(__floats2half2_rn(fmaxf(p0[0] + bb0, 0.f),
                                              fmaxf(p0[1] + bb1, 0.f)));
                af[1] = h2u(__floats2half2_rn(fmaxf(p0[2] + bb0, 0.f),
                                              fmaxf(p0[3] + bb1, 0.f)));
                af[2] = h2u(__floats2half2_rn(fmaxf(p1[0] + bb2, 0.f),
                                              fmaxf(p1[1] + bb3, 0.f)));
                af[3] = h2u(__floats2half2_rn(fmaxf(p1[2] + bb2, 0.f),
                                              fmaxf(p1[3] + bb3, 0.f)));
                if (ks2 & 1) mma_f16(acc2b[mt], af, bv.x, bv.y);
                else         mma_f16(acc2a[mt], af, bv.x, bv.y);
            }
        }

        // qpart[p] stores BEFORE bar1 (reader is 2 barriers upstream; safe)
        if (tig < 2) {
            #pragma unroll
            for (int mt = 0; mt < 2; ++mt) {
                const int row0 = mw * 32 + mt * 16 + gid;
                qpart2[((p * 4 + nw) * 64 + row0) * 2 + tig] =
                    __floats2half2_rn(acc2a[mt][0] + acc2b[mt][0],
                                      acc2a[mt][1] + acc2b[mt][1]);
                qpart2[((p * 4 + nw) * 64 + row0 + 8) * 2 + tig] =
                    __floats2half2_rn(acc2a[mt][2] + acc2b[mt][2],
                                      acc2a[mt][3] + acc2b[mt][3]);
            }
        }
        __syncthreads();     // bar1: A reads done; publishes qpart[p]

        // tail epoch: stage next tile's A only
        stsA();
        __syncthreads();     // bar2: publishes staged A

        // ---- fused reduce + quantum; overlaps next tile's mainloop ----
        {
            const int row = tid >> 2, q = tid & 3;
            float s = 0.f;
            #pragma unroll
            for (int ww = 0; ww < 4; ++ww) {
                const __half2 v = qpart2[((p * 4 + ww) * 64 + row) * 2 + (q >> 1)];
                s += (q & 1) ? __high2float(v) : __low2float(v);
            }
            const float qin = s + b2s[q];

            float cc, ssn;
            __sincosf(0.5f * qin, &ssn, &cc);
            float csc[4], css[4];
            #pragma unroll
            for (int k = 0; k < 4; ++k) {
                csc[k] = __shfl_xor_sync(0xffffffffu, cc,  q ^ k);
                css[k] = __shfl_xor_sync(0xffffffffu, ssn, q ^ k);
            }
            float v[16];
            #pragma unroll
            for (int idx = 0; idx < 16; ++idx)
                v[idx] = ((idx & 8) ? css[0] : csc[0])
                       * ((idx & 4) ? css[1] : csc[1])
                       * ((idx & 2) ? css[2] : csc[2])
                       * ((idx & 1) ? css[3] : csc[3]);
            float qo = 0.f;
            #pragma unroll
            for (int ii = 0; ii < 4; ++ii) {
                const int i = q * 4 + ii;
                float mv = 0.f;
                #pragma unroll
                for (int j = 0; j < 16; ++j)
                    mv = fmaf(Ms[i * 17 + j], v[j], mv);
                qo = fmaf(v[i], mv, qo);
            }
            qo += __shfl_xor_sync(0xffffffffu, qo, 1);
            qo += __shfl_xor_sync(0xffffffffu, qo, 2);
            if (q == 0)
                out[br * B_TOTAL + rowbase + row] = fmaf(qo, pp[0], pp[1]);
        }
        p ^= 1;
    }
}

extern "C" void kernel_launch(void* const* d_in, const int* in_sizes, int n_in,
                              void* d_out, int out_size) {
    const float* state  = (const float*)d_in[0];
    const float* action = (const float*)d_in[1];
    const float* q1_W1  = (const float*)d_in[2];
    const float* q1_b1  = (const float*)d_in[3];
    const float* q1_W2  = (const float*)d_in[4];
    const float* q1_b2  = (const float*)d_in[5];
    const float* q2_W1  = (const float*)d_in[6];
    const float* q2_b1  = (const float*)d_in[7];
    const float* q2_W2  = (const float*)d_in[8];
    const float* q2_b2  = (const float*)d_in[9];
    const float* q1_qw  = (const float*)d_in[10];
    const float* q2_qw  = (const float*)d_in[11];
    const float* q1_pw  = (const float*)d_in[12];
    const float* q1_pb  = (const float*)d_in[13];
    const float* q2_pw  = (const float*)d_in[14];
    const float* q2_pb  = (const float*)d_in[15];
    float* out = (float*)d_out;

    int dev = 0, nsm = 148;
    cudaGetDevice(&dev);
    cudaDeviceGetAttribute(&nsm, cudaDevAttrMultiProcessorCount, dev);
    if (nsm < 1) nsm = 1;

    cudaFuncSetAttribute(critic_mma, cudaFuncAttributeMaxDynamicSharedMemorySize,
                         SMEM_BYTES);

    setup_kernel<<<83, 256>>>(q1_qw, q2_qw, q1_W1, q2_W1, q1_W2, q2_W2);
    critic_mma<<<2 * nsm, NTHREADS, SMEM_BYTES>>>(
        state, action,
        q1_b1, q1_b2,
        q2_b1, q2_b2,
        q1_pw, q1_pb, q2_pw, q2_pb,
        out);
}

// round 15
// speedup vs baseline: 1.0273x; 1.0273x over previous
#include <cuda_runtime.h>
#include <cuda_fp16.h>
#include <math.h>
#include <cstdint>

#define B_TOTAL 131072
#define SD 128
#define AD 32
#define TILE_M 64
#define NTILES 2048            // per branch
#define NTHREADS 256

__device__ float d_M[2][256];
// B fragments for register residency: [br][ks(10)][w(8)][h(2)][lane(32)][4 u32]
__device__ uint32_t d_BfragR[2 * 10 * 8 * 2 * 32 * 4];
// fp16 B fragments GEMM2 (W2^T, n=8 padded): [br][ks(16)][lane(32)][2] half2
__device__ __half2 d_W2frag[2 * 16 * 32 * 2];

// ---- smem layout (byte offsets), one CTA/SM ----
#define OFF_A0    0            // [64][168] halfs = 21504B
#define OFF_A1    21504
#define OFF_B1S   43008        // 256 floats = 1024B
#define OFF_MS    44032        // 16x17 floats -> 1152B
#define OFF_QPART 45184        // [2][8][64][2] half2 = 8192B
#define OFF_B2S   53376        // 16B
#define OFF_PP    53392        // 8B
#define SMEM_BYTES 53408

#define A_PITCH 168            // halfs per row (160 data + 8 pad)
#define A_PITCH_B 336          // bytes

__device__ __forceinline__ uint32_t smem_u32(const void* p) {
    uint32_t a;
    asm("{ .reg .u64 t; cvta.to.shared.u64 t, %1; cvt.u32.u64 %0, t; }" : "=r"(a) : "l"(p));
    return a;
}
#define LDSM_X4(r0, r1, r2, r3, addr) \
    asm volatile("ldmatrix.sync.aligned.m8n8.x4.shared.b16 {%0,%1,%2,%3}, [%4];" \
        : "=r"(r0), "=r"(r1), "=r"(r2), "=r"(r3) : "r"(addr))

__device__ __forceinline__ void mma_f16(float* d, const uint32_t* a,
                                        uint32_t b0, uint32_t b1) {
    asm volatile(
        "mma.sync.aligned.m16n8k16.row.col.f32.f16.f16.f32 "
        "{%0,%1,%2,%3}, {%4,%5,%6,%7}, {%8,%9}, {%0,%1,%2,%3};"
        : "+f"(d[0]), "+f"(d[1]), "+f"(d[2]), "+f"(d[3])
        : "r"(a[0]), "r"(a[1]), "r"(a[2]), "r"(a[3]), "r"(b0), "r"(b1));
}
__device__ __forceinline__ uint32_t h2u(__half2 h) { return *(uint32_t*)&h; }

// ---------------------------------------------------------------------------
// Setup: blocks 0,1 -> M; 2..41 -> W1 B-register table; 42 -> W2 frags.
// ---------------------------------------------------------------------------
__global__ void setup_kernel(const float* __restrict__ qw1,
                             const float* __restrict__ qw2,
                             const float* __restrict__ W1a,
                             const float* __restrict__ W1b,
                             const float* __restrict__ W2a,
                             const float* __restrict__ W2b) {
    if (blockIdx.x < 2) {
        const int br = blockIdx.x;
        const int t  = threadIdx.x;
        const int j  = t >> 4;
        const int m  = t & 15;
        const float* qw = br ? qw2 : qw1;
        __shared__ float Ur[16][17];
        __shared__ float Ui[16][17];

        float sr = (m == j) ? 1.f : 0.f;
        float si = 0.f;

        for (int l = 0; l < 2; ++l) {
            #pragma unroll
            for (int i = 0; i < 4; ++i) {
                const int st = 8 >> i;
                float cc, ss, pr, pi;
                sincosf(0.5f * qw[(l * 4 + i) * 3 + 0], &ss, &cc);   // RX
                pr = __shfl_xor_sync(0xffffffffu, sr, st);
                pi = __shfl_xor_sync(0xffffffffu, si, st);
                { float nr = cc * sr + ss * pi, ni = cc * si - ss * pr;
                  sr = nr; si = ni; }
                sincosf(0.5f * qw[(l * 4 + i) * 3 + 1], &ss, &cc);   // RY
                pr = __shfl_xor_sync(0xffffffffu, sr, st);
                pi = __shfl_xor_sync(0xffffffffu, si, st);
                { const float e = (m & st) ? ss : -ss;
                  float nr = cc * sr + e * pr, ni = cc * si + e * pi;
                  sr = nr; si = ni; }
                sincosf(0.5f * qw[(l * 4 + i) * 3 + 2], &ss, &cc);   // RZ
                { const float e = (m & st) ? -ss : ss;
                  float nr = cc * sr + e * si, ni = cc * si - e * sr;
                  sr = nr; si = ni; }
            }
            #pragma unroll
            for (int e = 0; e < 4; ++e) {
                const int sc  = 8 >> e;
                const int stt = 8 >> ((e + 1) & 3);
                const float pr = __shfl_xor_sync(0xffffffffu, sr, stt);
                const float pi = __shfl_xor_sync(0xffffffffu, si, stt);
                if (m & sc) { sr = pr; si = pi; }
            }
        }
        Ur[m][j] = sr;
        Ui[m][j] = si;
        __syncthreads();
        {
            const int i = t >> 4, jj = t & 15;
            float acc = 0.f;
            #pragma unroll
            for (int k = 0; k < 16; ++k) {
                const float d = (k < 8) ? 1.f : -1.f;
                acc += d * (Ur[k][i] * Ur[k][jj] + Ui[k][i] * Ui[k][jj]);
            }
            d_M[br][i * 16 + jj] = acc;
        }
    } else if (blockIdx.x < 42) {
        // B-register table: idx -> (br, ks, w, h, lane); write 4 u32s.
        // uint4 element j: nt = h*2 + (j>>1), reg = j&1 (b0/b1).
        const int idx = (blockIdx.x - 2) * 256 + threadIdx.x;   // 0..10239
        const int lane = idx & 31;
        const int h    = (idx >> 5) & 1;
        const int w    = (idx >> 6) & 7;
        const int t    = idx >> 9;        // br*10 + ks
        const int ks   = t % 10;
        const int br   = t / 10;
        const float* W1 = br ? W1b : W1a;
        uint32_t* dst = d_BfragR + (size_t)idx * 4;
        #pragma unroll
        for (int j = 0; j < 4; ++j) {
            const int nt  = h * 2 + (j >> 1);
            const int n   = w * 32 + nt * 8 + (lane >> 2);
            const int k   = ks * 16 + (lane & 3) * 2 + (j & 1) * 8;
            const __half2 v = __floats2half2_rn(W1[n * 160 + k], W1[n * 160 + k + 1]);
            dst[j] = *(const uint32_t*)&v;
        }
    } else if (blockIdx.x == 42) {
        #pragma unroll
        for (int rep = 0; rep < 4; ++rep) {
            const int idx = threadIdx.x + rep * 256;   // 0..1023
            const int br   = idx >> 9;
            const int rem  = idx & 511;
            const int ks   = rem >> 5;
            const int lane = rem & 31;
            const float* W2 = br ? W2b : W2a;
            const int n  = lane >> 2;
            const int k0 = ks * 16 + (lane & 3) * 2;
            __half2 v0 = __floats2half2_rn(0.f, 0.f), v1 = v0;
            if (n < 4) {
                v0 = __floats2half2_rn(W2[n * 256 + k0],     W2[n * 256 + k0 + 1]);
                v1 = __floats2half2_rn(W2[n * 256 + k0 + 8], W2[n * 256 + k0 + 9]);
            }
            d_W2frag[idx * 2]     = v0;
            d_W2frag[idx * 2 + 1] = v1;
        }
    }
}

// ---------------------------------------------------------------------------
// Persistent fused critic: 1 CTA/SM, 256 threads, 8 warps x (64 rows x 32
// cols). B (W1) fragments live in REGISTERS (80/thread) — zero B smem reads.
// ---------------------------------------------------------------------------
__global__ __launch_bounds__(NTHREADS, 1)
void critic_mma(const float* __restrict__ state,
                const float* __restrict__ action,
                const float* __restrict__ b1a, const float* __restrict__ b2a,
                const float* __restrict__ b1b, const float* __restrict__ b2b,
                const float* __restrict__ pwa, const float* __restrict__ pba,
                const float* __restrict__ pwb, const float* __restrict__ pbb,
                float* __restrict__ out) {
    extern __shared__ char smem[];
    const uint32_t sb = smem_u32(smem);
    const int tid  = threadIdx.x;
    const int w    = tid >> 5;      // 0..7 (n-slab)
    const int lane = tid & 31;
    const int gid  = lane >> 2;
    const int tig  = lane & 3;

    const int br   = blockIdx.x & 1;
    const int cid  = blockIdx.x >> 1;
    const int ncta = gridDim.x >> 1;
    const int per  = NTILES / ncta;
    const int rem  = NTILES % ncta;
    const int t0   = cid * per + (cid < rem ? cid : rem);
    const int cnt  = per + (cid < rem ? 1 : 0);

    const float* b1 = br ? b1b : b1a;
    const float* b2 = br ? b2b : b2a;
    const float* pw = br ? pwb : pwa;
    const float* pb = br ? pbb : pba;

    float*   b1s    = (float*)(smem + OFF_B1S);
    float*   Ms     = (float*)(smem + OFF_MS);      // pitch 17
    __half2* qpart2 = (__half2*)(smem + OFF_QPART); // [2][8][64][2] half2
    float*   b2s    = (float*)(smem + OFF_B2S);
    float*   pp     = (float*)(smem + OFF_PP);

    // --- B fragments -> registers (loaded once) ---
    uint4 Breg[10][2];
    {
        const uint4* src = (const uint4*)d_BfragR;
        #pragma unroll
        for (int ks = 0; ks < 10; ++ks)
            #pragma unroll
            for (int h = 0; h < 2; ++h)
                Breg[ks][h] = src[(((br * 10 + ks) * 8 + w) * 2 + h) * 32 + lane];
    }
    // --- W2 fragments -> registers (4 u32) ---
    uint2 W2reg[2];
    #pragma unroll
    for (int s = 0; s < 2; ++s)
        W2reg[s] = *(const uint2*)(d_W2frag + ((br * 16 + 2 * w + s) * 32 + lane) * 2);

    // --- A staging: 64 x 160 fp32 -> regs -> fp16 smem ---
    float4 aregs[10];
    auto ldgA = [&](int rowbase) {
        #pragma unroll
        for (int ch = 0; ch < 5; ++ch)
            #pragma unroll
            for (int i = 0; i < 2; ++i) {
                const int e = tid + i * NTHREADS;     // 0..511
                const int r = e >> 3, seg = e & 7;    // 64 rows x 8 segs
                const float* src = (ch < 4)
                    ? state  + (size_t)(rowbase + r) * SD + ch * 32 + seg * 4
                    : action + (size_t)(rowbase + r) * AD + seg * 4;
                aregs[ch * 2 + i] = *(const float4*)src;
            }
    };
    auto stsA = [&](char* Ab) {
        __half* As = (__half*)Ab;
        #pragma unroll
        for (int ch = 0; ch < 5; ++ch)
            #pragma unroll
            for (int i = 0; i < 2; ++i) {
                const int e = tid + i * NTHREADS;
                const int r = e >> 3, seg = e & 7;
                const float4 v = aregs[ch * 2 + i];
                __half2 h0 = __floats2half2_rn(v.x, v.y);
                __half2 h1 = __floats2half2_rn(v.z, v.w);
                *(uint2*)(As + r * A_PITCH + ch * 32 + seg * 4) =
                    make_uint2(h2u(h0), h2u(h1));
            }
    };

    // --- prologue: tables + A(tile0) ---
    b1s[tid] = b1[tid];
    Ms[(tid >> 4) * 17 + (tid & 15)] = d_M[br][tid];
    if (tid < 4) b2s[tid] = b2[tid];
    if (tid == 0) { pp[0] = pw[0]; pp[1] = pb[0]; }
    ldgA(t0 * TILE_M);
    stsA(smem + OFF_A0);
    __syncthreads();

    // ldmatrix A per-lane address pieces
    const uint32_t lrow  = (lane & 7) + (((lane >> 3) & 1) << 3);
    const uint32_t lkofs = (lane >> 4) * 16;   // bytes
    const uint32_t AbBase = lrow * A_PITCH_B + lkofs;

    int p = 0;
    for (int it = 0; it < cnt; ++it) {
        const int rowbase = (t0 + it) * TILE_M;
        const int nrb = (it + 1 < cnt) ? (t0 + it + 1) * TILE_M : rowbase;
        const uint32_t Ab0 = sb + (p ? OFF_A1 : OFF_A0) + AbBase;

        float acc[4][4][4];   // [mt 16-row][nt 8-col][regs]
        #pragma unroll
        for (int mt = 0; mt < 4; ++mt)
            #pragma unroll
            for (int nt = 0; nt < 4; ++nt)
                #pragma unroll
                for (int i = 0; i < 4; ++i) acc[mt][nt][i] = 0.f;

        // ---- GEMM1: 10 ksteps; B from registers, A via LDSM ----
        #pragma unroll
        for (int ks = 0; ks < 10; ++ks) {
            if (ks == 6) ldgA(nrb);
            uint32_t a[4][4];
            #pragma unroll
            for (int mt = 0; mt < 4; ++mt)
                LDSM_X4(a[mt][0], a[mt][1], a[mt][2], a[mt][3],
                        Ab0 + mt * 16 * A_PITCH_B + ks * 32);
            #pragma unroll
            for (int mt = 0; mt < 4; ++mt) {
                mma_f16(acc[mt][0], a[mt], Breg[ks][0].x, Breg[ks][0].y);
                mma_f16(acc[mt][1], a[mt], Breg[ks][0].z, Breg[ks][0].w);
                mma_f16(acc[mt][2], a[mt], Breg[ks][1].x, Breg[ks][1].y);
                mma_f16(acc[mt][3], a[mt], Breg[ks][1].z, Breg[ks][1].w);
            }
        }

        // ---- GEMM2 (all-register): h = relu(acc + b1) -> 8 HMMA ----
        float acc2[4][4];
        #pragma unroll
        for (int mt = 0; mt < 4; ++mt)
            #pragma unroll
            for (int i = 0; i < 4; ++i) acc2[mt][i] = 0.f;

        #pragma unroll
        for (int s = 0; s < 2; ++s) {
            const int c0 = w * 32 + s * 16 + tig * 2;
            const float bb0 = b1s[c0],     bb1 = b1s[c0 + 1];
            const float bb2 = b1s[c0 + 8], bb3 = b1s[c0 + 9];
            #pragma unroll
            for (int mt = 0; mt < 4; ++mt) {
                const float* p0 = acc[mt][2 * s];
                const float* p1 = acc[mt][2 * s + 1];
                uint32_t af[4];
                af[0] = h2u(__floats2half2_rn(fmaxf(p0[0] + bb0, 0.f),
                                              fmaxf(p0[1] + bb1, 0.f)));
                af[1] = h2u(__floats2half2_rn(fmaxf(p0[2] + bb0, 0.f),
                                              fmaxf(p0[3] + bb1, 0.f)));
                af[2] = h2u(__floats2half2_rn(fmaxf(p1[0] + bb2, 0.f),
                                              fmaxf(p1[1] + bb3, 0.f)));
                af[3] = h2u(__floats2half2_rn(fmaxf(p1[2] + bb2, 0.f),
                                              fmaxf(p1[3] + bb3, 0.f)));
                mma_f16(acc2[mt], af, W2reg[s].x, W2reg[s].y);
            }
        }

        // qpart[p] stores before bar1 (reader finished 2 barriers ago)
        if (tig < 2) {
            #pragma unroll
            for (int mt = 0; mt < 4; ++mt) {
                const int row0 = mt * 16 + gid;
                qpart2[((p * 8 + w) * 64 + row0) * 2 + tig] =
                    __floats2half2_rn(acc2[mt][0], acc2[mt][1]);
                qpart2[((p * 8 + w) * 64 + row0 + 8) * 2 + tig] =
                    __floats2half2_rn(acc2[mt][2], acc2[mt][3]);
            }
        }
        __syncthreads();     // bar1: A reads done; qpart[p] published

        stsA(smem + (p ? OFF_A0 : OFF_A1));
        __syncthreads();     // bar2: staged A published

        // ---- fused reduce + quantum (drifts into next mainloop via skew) ----
        {
            const int row = tid >> 2, q = tid & 3;
            float s = 0.f;
            #pragma unroll
            for (int ww = 0; ww < 8; ++ww) {
                const __half2 v = qpart2[((p * 8 + ww) * 64 + row) * 2 + (q >> 1)];
                s += (q & 1) ? __high2float(v) : __low2float(v);
            }
            const float qin = s + b2s[q];

            float cc, ssn;
            __sincosf(0.5f * qin, &ssn, &cc);
            float csc[4], css[4];
            #pragma unroll
            for (int k = 0; k < 4; ++k) {
                csc[k] = __shfl_xor_sync(0xffffffffu, cc,  q ^ k);
                css[k] = __shfl_xor_sync(0xffffffffu, ssn, q ^ k);
            }
            float v[16];
            #pragma unroll
            for (int idx = 0; idx < 16; ++idx)
                v[idx] = ((idx & 8) ? css[0] : csc[0])
                       * ((idx & 4) ? css[1] : csc[1])
                       * ((idx & 2) ? css[2] : csc[2])
                       * ((idx & 1) ? css[3] : csc[3]);
            float qo = 0.f;
            #pragma unroll
            for (int ii = 0; ii < 4; ++ii) {
                const int i = q * 4 + ii;
                float mv = 0.f;
                #pragma unroll
                for (int j = 0; j < 16; ++j)
                    mv = fmaf(Ms[i * 17 + j], v[j], mv);
                qo = fmaf(v[i], mv, qo);
            }
            qo += __shfl_xor_sync(0xffffffffu, qo, 1);
            qo += __shfl_xor_sync(0xffffffffu, qo, 2);
            if (q == 0)
                out[br * B_TOTAL + rowbase + row] = fmaf(qo, pp[0], pp[1]);
        }
        p ^= 1;
    }
}

extern "C" void kernel_launch(void* const* d_in, const int* in_sizes, int n_in,
                              void* d_out, int out_size) {
    const float* state  = (const float*)d_in[0];
    const float* action = (const float*)d_in[1];
    const float* q1_W1  = (const float*)d_in[2];
    const float* q1_b1  = (const float*)d_in[3];
    const float* q1_W2  = (const float*)d_in[4];
    const float* q1_b2  = (const float*)d_in[5];
    const float* q2_W1  = (const float*)d_in[6];
    const float* q2_b1  = (const float*)d_in[7];
    const float* q2_W2  = (const float*)d_in[8];
    const float* q2_b2  = (const float*)d_in[9];
    const float* q1_qw  = (const float*)d_in[10];
    const float* q2_qw  = (const float*)d_in[11];
    const float* q1_pw  = (const float*)d_in[12];
    const float* q1_pb  = (const float*)d_in[13];
    const float* q2_pw  = (const float*)d_in[14];
    const float* q2_pb  = (const float*)d_in[15];
    float* out = (float*)d_out;

    int dev = 0, nsm = 148;
    cudaGetDevice(&dev);
    cudaDeviceGetAttribute(&nsm, cudaDevAttrMultiProcessorCount, dev);
    if (nsm < 2) nsm = 2;

    cudaFuncSetAttribute(critic_mma, cudaFuncAttributeMaxDynamicSharedMemorySize,
                         SMEM_BYTES);

    setup_kernel<<<43, 256>>>(q1_qw, q2_qw, q1_W1, q2_W1, q1_W2, q2_W2);
    critic_mma<<<nsm, NTHREADS, SMEM_BYTES>>>(
        state, action,
        q1_b1, q1_b2,
        q2_b1, q2_b2,
        q1_pw, q1_pb, q2_pw, q2_pb,
        out);
}

// round 16
// speedup vs baseline: 1.1354x; 1.1053x over previous
#include <cuda_runtime.h>
#include <cuda_fp16.h>
#include <math.h>
#include <cstdint>

#define B_TOTAL 131072
#define SD 128
#define AD 32
#define TILE_M 64
#define NTILES 2048            // per branch
#define NTHREADS 256

__device__ float d_M[2][256];
// B fragments for register residency: [br][ks(10)][w(8)][h(2)][lane(32)][4 u32]
__device__ uint32_t d_BfragR[2 * 10 * 8 * 2 * 32 * 4];
// fp16 B fragments GEMM2 (W2^T, n=8 padded): [br][ks(16)][lane(32)][2] half2
__device__ __half2 d_W2frag[2 * 16 * 32 * 2];

// ---- smem layout (byte offsets), one CTA/SM ----
#define OFF_A0    0            // [64][168] halfs = 21504B
#define OFF_A1    21504
#define OFF_B1S   43008        // 256 floats = 1024B
#define OFF_MS    44032        // 16x17 floats -> 1152B
#define OFF_QPART 45184        // [2][8][64][2] half2 = 8192B
#define OFF_B2S   53376        // 16B
#define OFF_PP    53392        // 8B
#define SMEM_BYTES 53408

#define A_PITCH 168            // halfs per row (160 data + 8 pad)
#define A_PITCH_B 336          // bytes

__device__ __forceinline__ uint32_t smem_u32(const void* p) {
    uint32_t a;
    asm("{ .reg .u64 t; cvta.to.shared.u64 t, %1; cvt.u32.u64 %0, t; }" : "=r"(a) : "l"(p));
    return a;
}
#define LDSM_X4(r0, r1, r2, r3, addr) \
    asm volatile("ldmatrix.sync.aligned.m8n8.x4.shared.b16 {%0,%1,%2,%3}, [%4];" \
        : "=r"(r0), "=r"(r1), "=r"(r2), "=r"(r3) : "r"(addr))

__device__ __forceinline__ void mma_f16(float* d, const uint32_t* a,
                                        uint32_t b0, uint32_t b1) {
    asm volatile(
        "mma.sync.aligned.m16n8k16.row.col.f32.f16.f16.f32 "
        "{%0,%1,%2,%3}, {%4,%5,%6,%7}, {%8,%9}, {%0,%1,%2,%3};"
        : "+f"(d[0]), "+f"(d[1]), "+f"(d[2]), "+f"(d[3])
        : "r"(a[0]), "r"(a[1]), "r"(a[2]), "r"(a[3]), "r"(b0), "r"(b1));
}
__device__ __forceinline__ uint32_t h2u(__half2 h) { return *(uint32_t*)&h; }

// ---------------------------------------------------------------------------
// Setup: blocks 0,1 -> M; 2..41 -> W1 B-register table; 42 -> W2 frags.
// ---------------------------------------------------------------------------
__global__ void setup_kernel(const float* __restrict__ qw1,
                             const float* __restrict__ qw2,
                             const float* __restrict__ W1a,
                             const float* __restrict__ W1b,
                             const float* __restrict__ W2a,
                             const float* __restrict__ W2b) {
    if (blockIdx.x < 2) {
        const int br = blockIdx.x;
        const int t  = threadIdx.x;
        const int j  = t >> 4;
        const int m  = t & 15;
        const float* qw = br ? qw2 : qw1;
        __shared__ float Ur[16][17];
        __shared__ float Ui[16][17];

        float sr = (m == j) ? 1.f : 0.f;
        float si = 0.f;

        for (int l = 0; l < 2; ++l) {
            #pragma unroll
            for (int i = 0; i < 4; ++i) {
                const int st = 8 >> i;
                float cc, ss, pr, pi;
                sincosf(0.5f * qw[(l * 4 + i) * 3 + 0], &ss, &cc);   // RX
                pr = __shfl_xor_sync(0xffffffffu, sr, st);
                pi = __shfl_xor_sync(0xffffffffu, si, st);
                { float nr = cc * sr + ss * pi, ni = cc * si - ss * pr;
                  sr = nr; si = ni; }
                sincosf(0.5f * qw[(l * 4 + i) * 3 + 1], &ss, &cc);   // RY
                pr = __shfl_xor_sync(0xffffffffu, sr, st);
                pi = __shfl_xor_sync(0xffffffffu, si, st);
                { const float e = (m & st) ? ss : -ss;
                  float nr = cc * sr + e * pr, ni = cc * si + e * pi;
                  sr = nr; si = ni; }
                sincosf(0.5f * qw[(l * 4 + i) * 3 + 2], &ss, &cc);   // RZ
                { const float e = (m & st) ? -ss : ss;
                  float nr = cc * sr + e * si, ni = cc * si - e * sr;
                  sr = nr; si = ni; }
            }
            #pragma unroll
            for (int e = 0; e < 4; ++e) {
                const int sc  = 8 >> e;
                const int stt = 8 >> ((e + 1) & 3);
                const float pr = __shfl_xor_sync(0xffffffffu, sr, stt);
                const float pi = __shfl_xor_sync(0xffffffffu, si, stt);
                if (m & sc) { sr = pr; si = pi; }
            }
        }
        Ur[m][j] = sr;
        Ui[m][j] = si;
        __syncthreads();
        {
            const int i = t >> 4, jj = t & 15;
            float acc = 0.f;
            #pragma unroll
            for (int k = 0; k < 16; ++k) {
                const float d = (k < 8) ? 1.f : -1.f;
                acc += d * (Ur[k][i] * Ur[k][jj] + Ui[k][i] * Ui[k][jj]);
            }
            d_M[br][i * 16 + jj] = acc;
        }
    } else if (blockIdx.x < 42) {
        const int idx = (blockIdx.x - 2) * 256 + threadIdx.x;   // 0..10239
        const int lane = idx & 31;
        const int h    = (idx >> 5) & 1;
        const int w    = (idx >> 6) & 7;
        const int t    = idx >> 9;        // br*10 + ks
        const int ks   = t % 10;
        const int br   = t / 10;
        const float* W1 = br ? W1b : W1a;
        uint32_t* dst = d_BfragR + (size_t)idx * 4;
        #pragma unroll
        for (int j = 0; j < 4; ++j) {
            const int nt  = h * 2 + (j >> 1);
            const int n   = w * 32 + nt * 8 + (lane >> 2);
            const int k   = ks * 16 + (lane & 3) * 2 + (j & 1) * 8;
            const __half2 v = __floats2half2_rn(W1[n * 160 + k], W1[n * 160 + k + 1]);
            dst[j] = *(const uint32_t*)&v;
        }
    } else if (blockIdx.x == 42) {
        #pragma unroll
        for (int rep = 0; rep < 4; ++rep) {
            const int idx = threadIdx.x + rep * 256;   // 0..1023
            const int br   = idx >> 9;
            const int rem  = idx & 511;
            const int ks   = rem >> 5;
            const int lane = rem & 31;
            const float* W2 = br ? W2b : W2a;
            const int n  = lane >> 2;
            const int k0 = ks * 16 + (lane & 3) * 2;
            __half2 v0 = __floats2half2_rn(0.f, 0.f), v1 = v0;
            if (n < 4) {
                v0 = __floats2half2_rn(W2[n * 256 + k0],     W2[n * 256 + k0 + 1]);
                v1 = __floats2half2_rn(W2[n * 256 + k0 + 8], W2[n * 256 + k0 + 9]);
            }
            d_W2frag[idx * 2]     = v0;
            d_W2frag[idx * 2 + 1] = v1;
        }
    }
}

// ---------------------------------------------------------------------------
// Persistent fused critic: 1 CTA/SM, 256 threads, B in registers, SINGLE
// barrier per tile, reduce+quantum of tile t deferred into tile t+1's
// mainloop (4 chunks interleaved with HMMA ksteps).
// ---------------------------------------------------------------------------
__global__ __launch_bounds__(NTHREADS, 1)
void critic_mma(const float* __restrict__ state,
                const float* __restrict__ action,
                const float* __restrict__ b1a, const float* __restrict__ b2a,
                const float* __restrict__ b1b, const float* __restrict__ b2b,
                const float* __restrict__ pwa, const float* __restrict__ pba,
                const float* __restrict__ pwb, const float* __restrict__ pbb,
                float* __restrict__ out) {
    extern __shared__ char smem[];
    const uint32_t sb = smem_u32(smem);
    const int tid  = threadIdx.x;
    const int w    = tid >> 5;      // 0..7 (n-slab)
    const int lane = tid & 31;
    const int gid  = lane >> 2;
    const int tig  = lane & 3;
    const int rrow = tid >> 2;      // reduce: row, and q = tid & 3
    const int rq   = tid & 3;

    const int br   = blockIdx.x & 1;
    const int cid  = blockIdx.x >> 1;
    const int ncta = gridDim.x >> 1;
    const int per  = NTILES / ncta;
    const int rem  = NTILES % ncta;
    const int t0   = cid * per + (cid < rem ? cid : rem);
    const int cnt  = per + (cid < rem ? 1 : 0);

    const float* b1 = br ? b1b : b1a;
    const float* b2 = br ? b2b : b2a;
    const float* pw = br ? pwb : pwa;
    const float* pb = br ? pbb : pba;

    float*   b1s    = (float*)(smem + OFF_B1S);
    float*   Ms     = (float*)(smem + OFF_MS);      // pitch 17
    __half2* qpart2 = (__half2*)(smem + OFF_QPART); // [2][8][64][2] half2
    float*   b2s    = (float*)(smem + OFF_B2S);
    float*   pp     = (float*)(smem + OFF_PP);

    // --- B fragments -> registers (loaded once) ---
    uint4 Breg[10][2];
    {
        const uint4* src = (const uint4*)d_BfragR;
        #pragma unroll
        for (int ks = 0; ks < 10; ++ks)
            #pragma unroll
            for (int h = 0; h < 2; ++h)
                Breg[ks][h] = src[(((br * 10 + ks) * 8 + w) * 2 + h) * 32 + lane];
    }
    uint2 W2reg[2];
    #pragma unroll
    for (int s = 0; s < 2; ++s)
        W2reg[s] = *(const uint2*)(d_W2frag + ((br * 16 + 2 * w + s) * 32 + lane) * 2);

    // --- A staging ---
    float4 aregs[10];
    auto ldgA = [&](int rowbase) {
        #pragma unroll
        for (int ch = 0; ch < 5; ++ch)
            #pragma unroll
            for (int i = 0; i < 2; ++i) {
                const int e = tid + i * NTHREADS;
                const int r = e >> 3, seg = e & 7;
                const float* src = (ch < 4)
                    ? state  + (size_t)(rowbase + r) * SD + ch * 32 + seg * 4
                    : action + (size_t)(rowbase + r) * AD + seg * 4;
                aregs[ch * 2 + i] = *(const float4*)src;
            }
    };
    auto stsA = [&](char* Ab) {
        __half* As = (__half*)Ab;
        #pragma unroll
        for (int ch = 0; ch < 5; ++ch)
            #pragma unroll
            for (int i = 0; i < 2; ++i) {
                const int e = tid + i * NTHREADS;
                const int r = e >> 3, seg = e & 7;
                const float4 v = aregs[ch * 2 + i];
                __half2 h0 = __floats2half2_rn(v.x, v.y);
                __half2 h1 = __floats2half2_rn(v.z, v.w);
                *(uint2*)(As + r * A_PITCH + ch * 32 + seg * 4) =
                    make_uint2(h2u(h0), h2u(h1));
            }
    };

    // --- prologue ---
    b1s[tid] = b1[tid];
    Ms[(tid >> 4) * 17 + (tid & 15)] = d_M[br][tid];
    if (tid < 4) b2s[tid] = b2[tid];
    if (tid == 0) { pp[0] = pw[0]; pp[1] = pb[0]; }
    ldgA(t0 * TILE_M);
    stsA(smem + OFF_A0);
    __syncthreads();

    const uint32_t lrow  = (lane & 7) + (((lane >> 3) & 1) << 3);
    const uint32_t lkofs = (lane >> 4) * 16;
    const uint32_t AbBase = lrow * A_PITCH_B + lkofs;

    // deferred-reduce state (tile t reduced during tile t+1's mainloop)
    int   d_rb = 0, d_p = 0, d_valid = 0;
    float rd_cc = 0.f, rd_ss = 0.f;
    float rd_csc[4], rd_css[4];
    float rd_qo = 0.f;
    #pragma unroll
    for (int k = 0; k < 4; ++k) { rd_csc[k] = 0.f; rd_css[k] = 0.f; }

    int p = 0;
    for (int it = 0; it < cnt; ++it) {
        const int rowbase = (t0 + it) * TILE_M;
        const int nrb = (it + 1 < cnt) ? (t0 + it + 1) * TILE_M : rowbase;
        const uint32_t Ab0 = sb + (p ? OFF_A1 : OFF_A0) + AbBase;

        float acc[4][4][4];
        #pragma unroll
        for (int mt = 0; mt < 4; ++mt)
            #pragma unroll
            for (int nt = 0; nt < 4; ++nt)
                #pragma unroll
                for (int i = 0; i < 4; ++i) acc[mt][nt][i] = 0.f;

        // ---- GEMM1 mainloop with embedded deferred reduce chunks ----
        #pragma unroll
        for (int ks = 0; ks < 10; ++ks) {
            if (ks == 6) ldgA(nrb);
            uint32_t a[4][4];
            #pragma unroll
            for (int mt = 0; mt < 4; ++mt)
                LDSM_X4(a[mt][0], a[mt][1], a[mt][2], a[mt][3],
                        Ab0 + mt * 16 * A_PITCH_B + ks * 32);
            #pragma unroll
            for (int mt = 0; mt < 4; ++mt) {
                mma_f16(acc[mt][0], a[mt], Breg[ks][0].x, Breg[ks][0].y);
                mma_f16(acc[mt][1], a[mt], Breg[ks][0].z, Breg[ks][0].w);
                mma_f16(acc[mt][2], a[mt], Breg[ks][1].x, Breg[ks][1].y);
                mma_f16(acc[mt][3], a[mt], Breg[ks][1].z, Breg[ks][1].w);
            }

            // --- deferred reduce chunks (tile it-1), overlap HMMA ---
            if (ks == 0 && d_valid) {
                float s = 0.f;
                #pragma unroll
                for (int ww = 0; ww < 8; ++ww) {
                    const __half2 v = qpart2[((d_p * 8 + ww) * 64 + rrow) * 2 + (rq >> 1)];
                    s += (rq & 1) ? __high2float(v) : __low2float(v);
                }
                __sincosf(0.5f * (s + b2s[rq]), &rd_ss, &rd_cc);
            }
            if (ks == 2 && d_valid) {
                #pragma unroll
                for (int k = 0; k < 4; ++k) {
                    rd_csc[k] = __shfl_xor_sync(0xffffffffu, rd_cc, rq ^ k);
                    rd_css[k] = __shfl_xor_sync(0xffffffffu, rd_ss, rq ^ k);
                }
            }
            if (ks == 4 && d_valid) {
                float v[16];
                #pragma unroll
                for (int idx = 0; idx < 16; ++idx)
                    v[idx] = ((idx & 8) ? rd_css[0] : rd_csc[0])
                           * ((idx & 4) ? rd_css[1] : rd_csc[1])
                           * ((idx & 2) ? rd_css[2] : rd_csc[2])
                           * ((idx & 1) ? rd_css[3] : rd_csc[3]);
                float qo = 0.f;
                #pragma unroll
                for (int ii = 0; ii < 4; ++ii) {
                    const int i = rq * 4 + ii;
                    float mv = 0.f;
                    #pragma unroll
                    for (int j = 0; j < 16; ++j)
                        mv = fmaf(Ms[i * 17 + j], v[j], mv);
                    qo = fmaf(v[i], mv, qo);
                }
                rd_qo = qo;
            }
            if (ks == 7 && d_valid) {
                rd_qo += __shfl_xor_sync(0xffffffffu, rd_qo, 1);
                rd_qo += __shfl_xor_sync(0xffffffffu, rd_qo, 2);
                if (rq == 0)
                    out[br * B_TOTAL + d_rb + rrow] = fmaf(rd_qo, pp[0], pp[1]);
            }
        }

        // ---- GEMM2 (all-register) ----
        float acc2[4][4];
        #pragma unroll
        for (int mt = 0; mt < 4; ++mt)
            #pragma unroll
            for (int i = 0; i < 4; ++i) acc2[mt][i] = 0.f;

        #pragma unroll
        for (int s = 0; s < 2; ++s) {
            const int c0 = w * 32 + s * 16 + tig * 2;
            const float bb0 = b1s[c0],     bb1 = b1s[c0 + 1];
            const float bb2 = b1s[c0 + 8], bb3 = b1s[c0 + 9];
            #pragma unroll
            for (int mt = 0; mt < 4; ++mt) {
                const float* p0 = acc[mt][2 * s];
                const float* p1 = acc[mt][2 * s + 1];
                uint32_t af[4];
                af[0] = h2u(__floats2half2_rn(fmaxf(p0[0] + bb0, 0.f),
                                              fmaxf(p0[1] + bb1, 0.f)));
                af[1] = h2u(__floats2half2_rn(fmaxf(p0[2] + bb0, 0.f),
                                              fmaxf(p0[3] + bb1, 0.f)));
                af[2] = h2u(__floats2half2_rn(fmaxf(p1[0] + bb2, 0.f),
                                              fmaxf(p1[1] + bb3, 0.f)));
                af[3] = h2u(__floats2half2_rn(fmaxf(p1[2] + bb2, 0.f),
                                              fmaxf(p1[3] + bb3, 0.f)));
                mma_f16(acc2[mt], af, W2reg[s].x, W2reg[s].y);
            }
        }

        // stage next tile's A (buffer p^1: its previous readers all passed
        // the PREVIOUS barrier — single-barrier scheme is race-free)
        stsA(smem + (p ? OFF_A0 : OFF_A1));

        // qpart[p] stores
        if (tig < 2) {
            #pragma unroll
            for (int mt = 0; mt < 4; ++mt) {
                const int row0 = mt * 16 + gid;
                qpart2[((p * 8 + w) * 64 + row0) * 2 + tig] =
                    __floats2half2_rn(acc2[mt][0], acc2[mt][1]);
                qpart2[((p * 8 + w) * 64 + row0 + 8) * 2 + tig] =
                    __floats2half2_rn(acc2[mt][2], acc2[mt][3]);
            }
        }
        __syncthreads();     // the ONLY barrier: publishes staged A + qpart[p]

        d_rb = rowbase; d_p = p; d_valid = 1;
        p ^= 1;
    }

    // ---- drain: reduce of the final tile ----
    {
        float s = 0.f;
        #pragma unroll
        for (int ww = 0; ww < 8; ++ww) {
            const __half2 v = qpart2[((d_p * 8 + ww) * 64 + rrow) * 2 + (rq >> 1)];
            s += (rq & 1) ? __high2float(v) : __low2float(v);
        }
        float cc, ssn;
        __sincosf(0.5f * (s + b2s[rq]), &ssn, &cc);
        float csc[4], css[4];
        #pragma unroll
        for (int k = 0; k < 4; ++k) {
            csc[k] = __shfl_xor_sync(0xffffffffu, cc,  rq ^ k);
            css[k] = __shfl_xor_sync(0xffffffffu, ssn, rq ^ k);
        }
        float v[16];
        #pragma unroll
        for (int idx = 0; idx < 16; ++idx)
            v[idx] = ((idx & 8) ? css[0] : csc[0])
                   * ((idx & 4) ? css[1] : csc[1])
                   * ((idx & 2) ? css[2] : csc[2])
                   * ((idx & 1) ? css[3] : csc[3]);
        float qo = 0.f;
        #pragma unroll
        for (int ii = 0; ii < 4; ++ii) {
            const int i = rq * 4 + ii;
            float mv = 0.f;
            #pragma unroll
            for (int j = 0; j < 16; ++j)
                mv = fmaf(Ms[i * 17 + j], v[j], mv);
            qo = fmaf(v[i], mv, qo);
        }
        qo += __shfl_xor_sync(0xffffffffu, qo, 1);
        qo += __shfl_xor_sync(0xffffffffu, qo, 2);
        if (rq == 0)
            out[br * B_TOTAL + d_rb + rrow] = fmaf(qo, pp[0], pp[1]);
    }
}

extern "C" void kernel_launch(void* const* d_in, const int* in_sizes, int n_in,
                              void* d_out, int out_size) {
    const float* state  = (const float*)d_in[0];
    const float* action = (const float*)d_in[1];
    const float* q1_W1  = (const float*)d_in[2];
    const float* q1_b1  = (const float*)d_in[3];
    const float* q1_W2  = (const float*)d_in[4];
    const float* q1_b2  = (const float*)d_in[5];
    const float* q2_W1  = (const float*)d_in[6];
    const float* q2_b1  = (const float*)d_in[7];
    const float* q2_W2  = (const float*)d_in[8];
    const float* q2_b2  = (const float*)d_in[9];
    const float* q1_qw  = (const float*)d_in[10];
    const float* q2_qw  = (const float*)d_in[11];
    const float* q1_pw  = (const float*)d_in[12];
    const float* q1_pb  = (const float*)d_in[13];
    const float* q2_pw  = (const float*)d_in[14];
    const float* q2_pb  = (const float*)d_in[15];
    float* out = (float*)d_out;

    int dev = 0, nsm = 148;
    cudaGetDevice(&dev);
    cudaDeviceGetAttribute(&nsm, cudaDevAttrMultiProcessorCount, dev);
    if (nsm < 2) nsm = 2;

    cudaFuncSetAttribute(critic_mma, cudaFuncAttributeMaxDynamicSharedMemorySize,
                         SMEM_BYTES);

    setup_kernel<<<43, 256>>>(q1_qw, q2_qw, q1_W1, q2_W1, q1_W2, q2_W2);
    critic_mma<<<nsm, NTHREADS, SMEM_BYTES>>>(
        state, action,
        q1_b1, q1_b2,
        q2_b1, q2_b2,
        q1_pw, q1_pb, q2_pw, q2_pb,
        out);
}